// round 6
// baseline (speedup 1.0000x reference)
#include <cuda_runtime.h>

// RotationPerturbationLayer == bilinear sampling with zero padding (the dense
// [B,N,N] tent-weight einsum has <=4 nonzero taps per output coordinate).
//
// R5 change vs R3 kernel: branch-free taps. Invalid taps are handled by
// zeroing their WEIGHT (SEL, no branch) and clamping their ADDRESS into
// range, so all 12 image loads are unconditional straight-line LDGs ->
// ptxas front-batches them (MLP=12, single memory round-trip) and the
// BSSY/BSYNC regions from the old nested ifs disappear.
//
// B=8, C=3, H=W=64. One thread per (b, pixel), all 3 channels.
// 128 blocks x 256 threads = 32768 threads, single wave on 148 SMs.

#define BB 8
#define CC 3
#define HH 64
#define WW 64
#define NN (HH * WW)   // 4096

__global__ __launch_bounds__(256, 1)
void rotation_bilinear_kernel(const float* __restrict__ theta,
                              const float* __restrict__ image,
                              float* __restrict__ out)
{
    const int idx = blockIdx.x * blockDim.x + threadIdx.x;  // 0 .. B*N-1
    const int b = idx >> 12;        // / NN
    const int n = idx & (NN - 1);   // % NN
    const int y = n >> 6;           // / WW
    const int x = n & (WW - 1);     // % WW

    const float t = __ldg(theta + b);   // uniform per block (16 blocks/batch)
    float st, ct;
    __sincosf(t, &st, &ct);

    const float c_x = (WW - 1) * 0.5f;
    const float c_y = (HH - 1) * 0.5f;
    const float xr = (float)x - c_x;
    const float yr = (float)y - c_y;

    const float sx =  ct * xr + st * yr + c_x;
    const float sy = -st * xr + ct * yr + c_y;

    const float fx = floorf(sx);
    const float fy = floorf(sy);
    const int x0 = (int)fx;
    const int y0 = (int)fy;
    const int x1 = x0 + 1;
    const int y1 = y0 + 1;

    const float ax = sx - fx;       // tent weight toward x1
    const float ay = sy - fy;

    // Zero weights for out-of-range taps (SEL, branch-free); clamp addresses.
    const float bxv = ((unsigned)x0 < (unsigned)WW) ? (1.0f - ax) : 0.0f;
    const float axv = ((unsigned)x1 < (unsigned)WW) ? ax          : 0.0f;
    const float byv = ((unsigned)y0 < (unsigned)HH) ? (1.0f - ay) : 0.0f;
    const float ayv = ((unsigned)y1 < (unsigned)HH) ? ay          : 0.0f;

    const int x0c = min(max(x0, 0), WW - 1);
    const int x1c = min(max(x1, 0), WW - 1);
    const int y0c = min(max(y0, 0), HH - 1);
    const int y1c = min(max(y1, 0), HH - 1);

    const int p00 = y0c * WW + x0c;
    const int p01 = y0c * WW + x1c;
    const int p10 = y1c * WW + x0c;
    const int p11 = y1c * WW + x1c;

    // 12 unconditional loads: front-batched, one memory round-trip.
    const float i00_0 = __ldg(image + p00);
    const float i01_0 = __ldg(image + p01);
    const float i10_0 = __ldg(image + p10);
    const float i11_0 = __ldg(image + p11);
    const float i00_1 = __ldg(image + NN + p00);
    const float i01_1 = __ldg(image + NN + p01);
    const float i10_1 = __ldg(image + NN + p10);
    const float i11_1 = __ldg(image + NN + p11);
    const float i00_2 = __ldg(image + 2 * NN + p00);
    const float i01_2 = __ldg(image + 2 * NN + p01);
    const float i10_2 = __ldg(image + 2 * NN + p10);
    const float i11_2 = __ldg(image + 2 * NN + p11);

    const float acc0 = byv * (bxv * i00_0 + axv * i01_0)
                     + ayv * (bxv * i10_0 + axv * i11_0);
    const float acc1 = byv * (bxv * i00_1 + axv * i01_1)
                     + ayv * (bxv * i10_1 + axv * i11_1);
    const float acc2 = byv * (bxv * i00_2 + axv * i01_2)
                     + ayv * (bxv * i10_2 + axv * i11_2);

    // out layout [B, C, H, W]; per-channel writes are warp-contiguous.
    float* ob = out + b * (CC * NN) + n;
    ob[0]      = acc0;
    ob[NN]     = acc1;
    ob[2 * NN] = acc2;
}

extern "C" void kernel_launch(void* const* d_in, const int* in_sizes, int n_in,
                              void* d_out, int out_size)
{
    const float* theta = (const float*)d_in[0];  // [B,1] = 8 floats
    const float* image = (const float*)d_in[1];  // [C,H,W] = 12288 floats
    float* out = (float*)d_out;                  // [B,C,H,W] = 98304 floats

    rotation_bilinear_kernel<<<(BB * NN) / 256, 256>>>(theta, image, out);
}